// round 5
// baseline (speedup 1.0000x reference)
#include <cuda_runtime.h>
#include <cuda_bf16.h>
#include <math.h>

// out[i] = z[i] * dot(pos[i], c),  c = (w_tp/(2*sqrt(3))) * W1 @ W2 @ (W3 @ ones(3))
// W1: [3,2], W2: [2,2], W3: [2,3]  row-major.
// 4 atoms/thread. pos staged through smem with coalesced global loads
// (direct per-thread loads are 48B-strided -> 12 lines/warp/instr; staging -> 4).

__global__ void __launch_bounds__(256)
atoms_kernel(const float4* __restrict__ pos4,
             const int4*   __restrict__ z4,
             float4*       __restrict__ out4,
             const float*  __restrict__ w_tp,
             const float*  __restrict__ W1,
             const float*  __restrict__ W2,
             const float*  __restrict__ W3,
             int n4, int n) {
    __shared__ float4 sp[768];                 // 256 threads * 3 float4 = 12 KB

    const int g0 = blockIdx.x * 256;           // first 4-atom group of this block
    const int p0 = g0 * 3;                     // first pos-float4 of this block
    const int rem_p = 3 * n4 - p0;             // float4s remaining from p0

    // Coalesced stage: consecutive threads load consecutive float4s.
    #pragma unroll
    for (int k = 0; k < 3; k++) {
        const int idx = threadIdx.x + k * 256;
        if (idx < rem_p) sp[idx] = __ldcs(&pos4[p0 + idx]);
    }

    // z load (already coalesced) — issue before the sync so it overlaps.
    const int g = g0 + threadIdx.x;
    int4 zz;
    const bool valid = (g < n4);
    if (valid) zz = __ldcs(&z4[g]);

    // Fold MLP into 3-vector c (uniform; L1-hit broadcasts; overlaps load latency).
    const float t30 = __ldg(&W3[0]) + __ldg(&W3[1]) + __ldg(&W3[2]);
    const float t31 = __ldg(&W3[3]) + __ldg(&W3[4]) + __ldg(&W3[5]);
    const float t20 = __ldg(&W2[0]) * t30 + __ldg(&W2[1]) * t31;
    const float t21 = __ldg(&W2[2]) * t30 + __ldg(&W2[3]) * t31;
    const float s   = __ldg(&w_tp[0]) * 0.28867513459481287f; // 1/(2*sqrt(3))
    const float c0  = (__ldg(&W1[0]) * t20 + __ldg(&W1[1]) * t21) * s;
    const float c1  = (__ldg(&W1[2]) * t20 + __ldg(&W1[3]) * t21) * s;
    const float c2  = (__ldg(&W1[4]) * t20 + __ldg(&W1[5]) * t21) * s;

    __syncthreads();

    if (valid) {
        // Conflict-free LDS: stride-3 float4 reads tile all 32 banks per phase.
        const float4 a = sp[3 * threadIdx.x + 0];
        const float4 b = sp[3 * threadIdx.x + 1];
        const float4 d = sp[3 * threadIdx.x + 2];
        float4 o;
        o.x = (a.x * c0 + a.y * c1 + a.z * c2) * (float)zz.x;
        o.y = (a.w * c0 + b.x * c1 + b.y * c2) * (float)zz.y;
        o.z = (b.z * c0 + b.w * c1 + d.x * c2) * (float)zz.z;
        o.w = (d.y * c0 + d.z * c1 + d.w * c2) * (float)zz.w;
        __stcs(&out4[g], o);                   // coalesced streaming store
    }

    // tail (n % 4 != 0) — dead for N=2M, kept for generality
    if ((n & 3) && g0 == 0 && threadIdx.x == 0) {
        const float* pos = (const float*)pos4;
        const int*   z   = (const int*)z4;
        float*       out = (float*)out4;
        for (int j = 4 * n4; j < n; j++) {
            out[j] = (pos[3 * j + 0] * c0 + pos[3 * j + 1] * c1 + pos[3 * j + 2] * c2)
                     * (float)z[j];
        }
    }
}

extern "C" void kernel_launch(void* const* d_in, const int* in_sizes, int n_in,
                              void* d_out, int out_size) {
    const float* pos  = (const float*)d_in[0];   // [N,3] f32
    const int*   z    = (const int*)d_in[1];     // [N]   i32
    const float* w_tp = (const float*)d_in[2];   // []    f32
    const float* W1   = (const float*)d_in[3];   // [3,2] f32
    const float* W2   = (const float*)d_in[4];   // [2,2] f32
    const float* W3   = (const float*)d_in[5];   // [2,3] f32
    float* out = (float*)d_out;

    const int n  = in_sizes[1];  // N atoms
    const int n4 = n >> 2;       // 4-atom groups

    const int threads = 256;
    int blocks = (n4 + threads - 1) / threads;
    if (blocks < 1) blocks = 1;
    atoms_kernel<<<blocks, threads>>>((const float4*)pos, (const int4*)z,
                                      (float4*)out, w_tp, W1, W2, W3, n4, n);
}

// round 6
// speedup vs baseline: 1.2656x; 1.2656x over previous
#include <cuda_runtime.h>
#include <cuda_bf16.h>
#include <math.h>

// out[i] = z[i] * dot(pos[i], c),  c = (w_tp/(2*sqrt(3))) * W1 @ W2 @ (W3 @ ones(3))
// W1: [3,2], W2: [2,2], W3: [2,3]  row-major.
// Persistent grid-stride: exactly 8 blocks/SM -> one full wave, no partial-wave idle.
// 4 atoms/thread/iter, direct float4 loads (R4 body, best measured).

__global__ void __launch_bounds__(256)
atoms_kernel(const float4* __restrict__ pos4,
             const int4*   __restrict__ z4,
             float4*       __restrict__ out4,
             const float*  __restrict__ w_tp,
             const float*  __restrict__ W1,
             const float*  __restrict__ W2,
             const float*  __restrict__ W3,
             int n4, int n) {
    // Fold MLP into 3-vector c (uniform; L1-hit broadcasts)
    const float t30 = __ldg(&W3[0]) + __ldg(&W3[1]) + __ldg(&W3[2]);
    const float t31 = __ldg(&W3[3]) + __ldg(&W3[4]) + __ldg(&W3[5]);
    const float t20 = __ldg(&W2[0]) * t30 + __ldg(&W2[1]) * t31;
    const float t21 = __ldg(&W2[2]) * t30 + __ldg(&W2[3]) * t31;
    const float s   = __ldg(&w_tp[0]) * 0.28867513459481287f; // 1/(2*sqrt(3))
    const float c0  = (__ldg(&W1[0]) * t20 + __ldg(&W1[1]) * t21) * s;
    const float c1  = (__ldg(&W1[2]) * t20 + __ldg(&W1[3]) * t21) * s;
    const float c2  = (__ldg(&W1[4]) * t20 + __ldg(&W1[5]) * t21) * s;

    const int stride = gridDim.x * blockDim.x;
    for (int i = blockIdx.x * blockDim.x + threadIdx.x; i < n4; i += stride) {
        const float4 a  = __ldcs(&pos4[3 * i + 0]);
        const float4 b  = __ldcs(&pos4[3 * i + 1]);
        const float4 d  = __ldcs(&pos4[3 * i + 2]);
        const int4   zz = __ldcs(&z4[i]);
        float4 o;
        o.x = (a.x * c0 + a.y * c1 + a.z * c2) * (float)zz.x;
        o.y = (a.w * c0 + b.x * c1 + b.y * c2) * (float)zz.y;
        o.z = (b.z * c0 + b.w * c1 + d.x * c2) * (float)zz.z;
        o.w = (d.y * c0 + d.z * c1 + d.w * c2) * (float)zz.w;
        __stcs(&out4[i], o);
    }

    // tail (n % 4 != 0) — dead for N=2M, kept for generality
    if ((n & 3) && blockIdx.x == 0 && threadIdx.x == 0) {
        const float* pos = (const float*)pos4;
        const int*   z   = (const int*)z4;
        float*       out = (float*)out4;
        for (int j = 4 * n4; j < n; j++) {
            out[j] = (pos[3 * j + 0] * c0 + pos[3 * j + 1] * c1 + pos[3 * j + 2] * c2)
                     * (float)z[j];
        }
    }
}

extern "C" void kernel_launch(void* const* d_in, const int* in_sizes, int n_in,
                              void* d_out, int out_size) {
    const float* pos  = (const float*)d_in[0];   // [N,3] f32
    const int*   z    = (const int*)d_in[1];     // [N]   i32
    const float* w_tp = (const float*)d_in[2];   // []    f32
    const float* W1   = (const float*)d_in[3];   // [3,2] f32
    const float* W2   = (const float*)d_in[4];   // [2,2] f32
    const float* W3   = (const float*)d_in[5];   // [2,3] f32
    float* out = (float*)d_out;

    const int n  = in_sizes[1];  // N atoms
    const int n4 = n >> 2;

    // One full wave: 8 blocks per SM (256 thr, 32 regs -> occ limit is 8).
    int sms = 148;
    cudaDeviceGetAttribute(&sms, cudaDevAttrMultiProcessorCount, 0);
    int blocks = 8 * sms;
    const int threads = 256;
    int needed = (n4 + threads - 1) / threads;
    if (blocks > needed) blocks = needed;     // small-n safety
    if (blocks < 1) blocks = 1;
    atoms_kernel<<<blocks, threads>>>((const float4*)pos, (const int4*)z,
                                      (float4*)out, w_tp, W1, W2, W3, n4, n);
}